// round 17
// baseline (speedup 1.0000x reference)
#include <cuda_runtime.h>
#include <cuda_bf16.h>

#define NB 8
#define NI 64
#define NO 64
#define NN 8192
#define NK 16
#define ND 3
#define NH1 16
#define NH2 32
#define TN 8
#define ROWS 128
#define NTHREADS 256
#define BON (NB*NO*NN)
#define SPN (NB*ND*NN)
#define CSTRIDE (NN*NK)

typedef unsigned long long u64;
typedef unsigned int u32;

// ---- smem layout (bytes): H planes + small arrays only ----
#define PPAD 136
#define SM_SH    0
#define SM_SL    8704
#define SM_SMALL 17408
#define SMEM_BYTES (SM_SMALL + 1248*4)   // 22400 B

// ---- global fragment buffers (built once per launch by prep kernel) ----
// g_bt[(nt*4+cp)*32+lane] = tf32 B frags for chunks 2cp,2cp+1 (GEMM1)
// g_b2f[(nt*2+s)*32+lane] = bf16 hi/lo B frags (GEMM2)
__device__ uint4 g_bt[8*4*32];
__device__ uint4 g_b2f[16*32];

__device__ __forceinline__ u64 pack2(float x, float y) {
    u64 r; asm("mov.b64 %0,{%1,%2};" : "=l"(r) : "f"(x), "f"(y)); return r;
}
__device__ __forceinline__ u64 fma2(u64 a, u64 b, u64 c) {
    u64 d; asm("fma.rn.f32x2 %0,%1,%2,%3;" : "=l"(d) : "l"(a), "l"(b), "l"(c)); return d;
}
__device__ __forceinline__ float2 unpack2(u64 v) {
    float2 f; asm("mov.b64 {%0,%1},%2;" : "=f"(f.x), "=f"(f.y) : "l"(v)); return f;
}
__device__ __forceinline__ u32 bf2bits(__nv_bfloat162 h) { return *reinterpret_cast<u32*>(&h); }
__device__ __forceinline__ u32 f2tf32(float f) {
    u32 r; asm("cvt.rna.tf32.f32 %0,%1;" : "=r"(r) : "f"(f)); return r;
}

__device__ __forceinline__ void split_pair(float f0, float f1, u32& hi, u32& lo) {
    __nv_bfloat162 hb = __float22bfloat162_rn(make_float2(f0, f1));
    float2 hf = __bfloat1622float2(hb);
    __nv_bfloat162 lb = __float22bfloat162_rn(make_float2(f0 - hf.x, f1 - hf.y));
    hi = bf2bits(hb); lo = bf2bits(lb);
}

#define MMA16816(c, a, b) \
    asm volatile("mma.sync.aligned.m16n8k16.row.col.f32.bf16.bf16.f32 " \
        "{%0,%1,%2,%3}, {%4,%5,%6,%7}, {%8,%9}, {%0,%1,%2,%3};" \
        : "+f"((c)[0]), "+f"((c)[1]), "+f"((c)[2]), "+f"((c)[3]) \
        : "r"((a).x), "r"((a).y), "r"((a).z), "r"((a).w), \
          "r"((b).x), "r"((b).y))

#define MMATF32(c, a, b0, b1) \
    asm volatile("mma.sync.aligned.m16n8k8.row.col.f32.tf32.tf32.f32 " \
        "{%0,%1,%2,%3}, {%4,%5,%6,%7}, {%8,%9}, {%0,%1,%2,%3};" \
        : "+f"((c)[0]), "+f"((c)[1]), "+f"((c)[2]), "+f"((c)[3]) \
        : "r"((a).x), "r"((a).y), "r"((a).z), "r"((a).w), \
          "r"(b0), "r"(b1))

// ================= prep kernel: build B fragments once =================
__global__ void pccn_prep(const float* __restrict__ weight, const float* __restrict__ W3)
{
    const int tid  = threadIdx.x;
    const int lane = tid & 31;
    const int gid  = lane >> 2;
    const int tig  = lane & 3;
    // GEMM1: tf32 B frags (rna), chunk pairs
    for (int blk = tid >> 5; blk < 32; blk += 8) {
        int nt = blk >> 2, cp = blk & 3;
        int n = 8*nt + gid;
        int k0 = 16*cp;
        u32 b00 = f2tf32(weight[(k0 + tig)*NO + n]);
        u32 b01 = f2tf32(weight[(k0 + tig + 4)*NO + n]);
        u32 b10 = f2tf32(weight[(k0 + 8 + tig)*NO + n]);
        u32 b11 = f2tf32(weight[(k0 + 8 + tig + 4)*NO + n]);
        g_bt[blk*32 + lane] = make_uint4(b00, b01, b10, b11);
    }
    // GEMM2: bf16 hi/lo frags
    for (int blk = tid >> 5; blk < 16; blk += 8) {
        int nt = blk >> 1, s = blk & 1;
        int n = 8*nt + gid, k0 = 16*s + 2*tig;
        float w00 = W3[k0*NO + n],     w01 = W3[(k0+1)*NO + n];
        float w10 = W3[(k0+8)*NO + n], w11 = W3[(k0+9)*NO + n];
        u32 h0,l0,h1,l1;
        split_pair(w00, w01, h0, l0);
        split_pair(w10, w11, h1, l1);
        g_b2f[blk*32 + lane] = make_uint4(h0, h1, l0, l1);
    }
}

__global__ void __launch_bounds__(NTHREADS, 3)
pccn_kernel(const float* __restrict__ input, const float* __restrict__ points,
            const float* __restrict__ support, const float* __restrict__ bias,
            const float* __restrict__ W1, const float* __restrict__ b1,
            const float* __restrict__ W2, const float* __restrict__ b2,
            const float* __restrict__ b3, float* __restrict__ out, int copy_sp)
{
    extern __shared__ char smemc[];
    u32* sHh = (u32*)(smemc + SM_SH);   // [jp][PPAD]
    u32* sHl = (u32*)(smemc + SM_SL);
    float* sW1   = (float*)(smemc + SM_SMALL);
    float* sb1   = sW1 + 48;
    float* sW2   = sb1 + 16;
    float* sb2   = sW2 + 512;
    float* sb3   = sb2 + 32;
    float* sBias = sb3 + 64;
    float* sOut  = sBias + 64;        // [n_local:8][o:64]

    const int tid  = threadIdx.x;
    const int warp = tid >> 5;
    const int lane = tid & 31;
    const int gid  = lane >> 2;
    const int tig  = lane & 3;
    const int ng   = warp & 3;        // rows 32ng..32ng+31 (n_local 2ng, 2ng+1)
    const int ch   = warp >> 2;       // nt in 4ch..4ch+3
    const int blk  = blockIdx.x;
    const int b    = blk >> 10;
    const int n0   = (blk & 1023) * TN;

    // ---- small arrays ----
    for (int idx = tid; idx < NH1*NH2; idx += NTHREADS) sW2[idx] = W2[idx];
    if (tid < 48) sW1[tid]  = W1[tid];
    if (tid < 16) sb1[tid]  = b1[tid];
    if (tid < 32) sb2[tid]  = b2[tid];
    if (tid < 64) sb3[tid]  = b3[tid];
    if (tid < 64) sBias[tid] = bias[tid];

    __syncthreads();   // MLP weights ready before MLP reads them

    // ========== coords + MLP, all 256 threads (row = tid&127, half ph) ==========
    {
        const int row = tid & 127;
        const int ph  = tid >> 7;              // 0: j 0..15, 1: j 16..31
        const int k = row & 15;
        const int n = n0 + (row >> 4);
        float p0 = points[(((size_t)b*ND + 0)*NN + n)*NK + k] - support[((size_t)b*ND + 0)*NN + n];
        float p1 = points[(((size_t)b*ND + 1)*NN + n)*NK + k] - support[((size_t)b*ND + 1)*NN + n];
        float p2 = points[(((size_t)b*ND + 2)*NN + n)*NK + k] - support[((size_t)b*ND + 2)*NN + n];
        float sq = p0*p0 + p1*p1 + p2*p2;
        float m = sq;
#pragma unroll
        for (int off = 8; off > 0; off >>= 1)
            m = fmaxf(m, __shfl_xor_sync(0xffffffffu, m, off));
        float maxi = sqrtf(m);
        maxi += (maxi == 0.0f) ? 1.0f : 0.0f;
        float inv = 1.0f / maxi;
        float x0 = p0*inv, x1 = p1*inv, x2 = p2*inv;

        float h1[NH1];
#pragma unroll
        for (int a = 0; a < NH1; a++) {
            float v = sb1[a] + x0*sW1[a] + x1*sW1[16 + a] + x2*sW1[32 + a];
            h1[a] = fmaxf(v, 0.0f);
        }
        u64 h2p[8];
        const u64* sb2p = (const u64*)(sb2 + 16*ph);
#pragma unroll
        for (int jj = 0; jj < 8; jj++) h2p[jj] = sb2p[jj];
#pragma unroll
        for (int a = 0; a < NH1; a++) {
            u64 xd = pack2(h1[a], h1[a]);
            const u64* wrow = (const u64*)(sW2 + a*NH2 + 16*ph);
#pragma unroll
            for (int jj = 0; jj < 8; jj++) h2p[jj] = fma2(xd, wrow[jj], h2p[jj]);
        }
#pragma unroll
        for (int jj = 0; jj < 8; jj++) {
            float2 v = unpack2(h2p[jj]);
            v.x = fmaxf(v.x, 0.0f); v.y = fmaxf(v.y, 0.0f);
            u32 hi, lo; split_pair(v.x, v.y, hi, lo);
            int jp = 8*ph + jj;                // pair (j=2jp, 2jp+1)
            sHh[jp*PPAD + row] = hi;
            sHl[jp*PPAD + row] = lo;
        }
    }

    __syncthreads();

    // ========== GEMMs: warp = (ng, ch): 2 m-tiles x 4 nt ==========
    float c1[2][4][4], c2[2][4][4];
#pragma unroll
    for (int m = 0; m < 2; m++)
#pragma unroll
        for (int nl = 0; nl < 4; nl++)
#pragma unroll
            for (int r = 0; r < 4; r++) { c1[m][nl][r] = 0.0f; c2[m][nl][r] = 0.0f; }

    const int rbase = 32*ng + gid;     // m-tile m adds 16m
    const float* xbase = input + (size_t)b*NI*CSTRIDE + (size_t)n0*NK;

    // GEMM1: C1 = X @ W (K=64), tf32 m16n8k8; A direct from GMEM (raw fp32 bits as tf32)
#pragma unroll
    for (int cp = 0; cp < 4; cp++) {
        uint4 a[2][2];
#pragma unroll
        for (int ck = 0; ck < 2; ck++) {
            const float* pk = xbase + (size_t)((2*cp + ck)*8 + tig)*CSTRIDE;
#pragma unroll
            for (int m = 0; m < 2; m++) {
                const int r = rbase + 16*m;
                a[ck][m].x = __float_as_uint(pk[r]);
                a[ck][m].y = __float_as_uint(pk[r + 8]);
                a[ck][m].z = __float_as_uint(pk[4*CSTRIDE + r]);
                a[ck][m].w = __float_as_uint(pk[4*CSTRIDE + r + 8]);
            }
        }
#pragma unroll
        for (int nl = 0; nl < 4; nl++) {
            uint4 bb = __ldg(&g_bt[((4*ch + nl)*4 + cp)*32 + lane]);
#pragma unroll
            for (int m = 0; m < 2; m++) {
                MMATF32(c1[m][nl], a[0][m], bb.x, bb.y);
                MMATF32(c1[m][nl], a[1][m], bb.z, bb.w);
            }
        }
    }
    // GEMM2: C2 = H @ W3 (K=32), bf16 3-product (unchanged)
#pragma unroll
    for (int s = 0; s < 2; s++) {
        const int kp = 8*s + tig;
        uint4 ah[2], al[2];
#pragma unroll
        for (int m = 0; m < 2; m++) {
            const int r = rbase + 16*m;
            ah[m].x = sHh[kp*PPAD + r];       al[m].x = sHl[kp*PPAD + r];
            ah[m].y = sHh[kp*PPAD + r + 8];   al[m].y = sHl[kp*PPAD + r + 8];
            ah[m].z = sHh[(kp+4)*PPAD + r];   al[m].z = sHl[(kp+4)*PPAD + r];
            ah[m].w = sHh[(kp+4)*PPAD + r + 8]; al[m].w = sHl[(kp+4)*PPAD + r + 8];
        }
#pragma unroll
        for (int nl = 0; nl < 4; nl++) {
            uint4 bb = __ldg(&g_b2f[((4*ch + nl)*2 + s)*32 + lane]);
            uint2 bh = make_uint2(bb.x, bb.y);
            uint2 bl = make_uint2(bb.z, bb.w);
#pragma unroll
            for (int m = 0; m < 2; m++) {
                MMA16816(c2[m][nl], ah[m], bh);
                MMA16816(c2[m][nl], ah[m], bl);
                MMA16816(c2[m][nl], al[m], bh);
            }
        }
    }

    // ========== combine: out[n,o] = sum_rows C1 * (C2 + b3) ==========
    {
#pragma unroll
        for (int m = 0; m < 2; m++) {
            const int n_loc = 2*ng + m;
#pragma unroll
            for (int nl = 0; nl < 4; nl++) {
                const int nt = 4*ch + nl;
                float b3e = sb3[8*nt + 2*tig];
                float b3o = sb3[8*nt + 2*tig + 1];
                float s0 = c1[m][nl][0]*(c2[m][nl][0] + b3e) + c1[m][nl][2]*(c2[m][nl][2] + b3e);
                float s1 = c1[m][nl][1]*(c2[m][nl][1] + b3o) + c1[m][nl][3]*(c2[m][nl][3] + b3o);
#pragma unroll
                for (int msk = 4; msk <= 16; msk <<= 1) {
                    s0 += __shfl_xor_sync(0xffffffffu, s0, msk);
                    s1 += __shfl_xor_sync(0xffffffffu, s1, msk);
                }
                if (lane < 4) {
                    sOut[n_loc*NO + 8*nt + 2*tig]     = s0;
                    sOut[n_loc*NO + 8*nt + 2*tig + 1] = s1;
                }
            }
        }
    }

    __syncthreads();

    // ========== epilogue: out (B, O, N) + bias ==========
    if (tid < 128) {
        int o = tid >> 1, half = tid & 1;
        float4 rr;
        rr.x = sOut[(half*4+0)*NO + o] + sBias[o];
        rr.y = sOut[(half*4+1)*NO + o] + sBias[o];
        rr.z = sOut[(half*4+2)*NO + o] + sBias[o];
        rr.w = sOut[(half*4+3)*NO + o] + sBias[o];
        *(float4*)(out + ((size_t)b*NO + o)*NN + n0 + half*4) = rr;
    }

    // ---- support_points passthrough ----
    if (copy_sp) {
        for (int idx = blk*NTHREADS + tid; idx < SPN; idx += gridDim.x*NTHREADS)
            out[BON + idx] = support[idx];
    }
}

extern "C" void kernel_launch(void* const* d_in, const int* in_sizes, int n_in,
                              void* d_out, int out_size) {
    const float* input   = (const float*)d_in[0];
    const float* points  = (const float*)d_in[1];
    const float* support = (const float*)d_in[2];
    const float* weight  = (const float*)d_in[3];
    const float* bias    = (const float*)d_in[4];
    const float* W1      = (const float*)d_in[5];
    const float* b1      = (const float*)d_in[6];
    const float* W2      = (const float*)d_in[7];
    const float* b2      = (const float*)d_in[8];
    const float* W3      = (const float*)d_in[9];
    const float* b3      = (const float*)d_in[10];

    int copy_sp = (out_size > BON) ? 1 : 0;
    pccn_prep<<<1, NTHREADS>>>(weight, W3);
    pccn_kernel<<<NB*(NN/TN), NTHREADS, SMEM_BYTES>>>(
        input, points, support, bias, W1, b1, W2, b2, b3,
        (float*)d_out, copy_sp);
}